// round 1
// baseline (speedup 1.0000x reference)
#include <cuda_runtime.h>

// AggregationLoss on GB300 (sm_103a).
// Two-pass: (1) per-batch segment sums over 33 labels via shared+global atomics,
// (2) per-pixel loss with shared LUT, block reduction, double global accumulator.
//
// Shapes (fixed by the problem): B=16, C=4, N = H*W = 736*736 = 541696.

#define BATCH 16
#define CHAN 4
#define NSEG 33
#define THREADS 256
#define PXPT 4  // pixels per thread (vectorized int4/float4)

// ---- device scratch (allocation-free) ----
__device__ float g_ksum[BATCH][NSEG];         // sum kmask over klab segments
__device__ float g_rsum[BATCH][NSEG];         // sum kmask over rlab segments (faithful to ref)
__device__ float g_psum[BATCH][NSEG][CHAN];   // sum pred over klab segments
__device__ int   g_kmax;                       // max klab of last batch
__device__ double g_acc;                       // loss accumulator

__global__ void init_scratch() {
    const int t = threadIdx.x;
    float* ks = &g_ksum[0][0];
    float* rs = &g_rsum[0][0];
    float* ps = &g_psum[0][0][0];
    for (int i = t; i < BATCH * NSEG; i += blockDim.x) { ks[i] = 0.f; rs[i] = 0.f; }
    for (int i = t; i < BATCH * NSEG * CHAN; i += blockDim.x) ps[i] = 0.f;
    if (t == 0) { g_kmax = 0; g_acc = 0.0; }
}

__global__ void __launch_bounds__(THREADS) pass1_kernel(
    const float* __restrict__ pred,   // [B, C, N]
    const float* __restrict__ kmask,  // [B, N]
    const int*   __restrict__ klab,   // [B, N]
    const int*   __restrict__ rlab,   // [B, N]
    int N)
{
    __shared__ float s_ksum[NSEG];
    __shared__ float s_rsum[NSEG];
    __shared__ float s_psum[NSEG][CHAN];

    const int t = threadIdx.x;
    const int b = blockIdx.y;

    for (int i = t; i < NSEG; i += THREADS) { s_ksum[i] = 0.f; s_rsum[i] = 0.f; }
    for (int i = t; i < NSEG * CHAN; i += THREADS) (&s_psum[0][0])[i] = 0.f;
    __syncthreads();

    const int n0 = (blockIdx.x * THREADS + t) * PXPT;
    const size_t base = (size_t)b * N;
    int local_kmax = 0;

    if (n0 + PXPT <= N) {
        int4   kl4 = *(const int4*)(klab + base + n0);
        int4   rl4 = *(const int4*)(rlab + base + n0);
        float4 km4 = *(const float4*)(kmask + base + n0);
        float4 pv[CHAN];
        const float* pb = pred + (size_t)b * CHAN * N + n0;
#pragma unroll
        for (int c = 0; c < CHAN; c++) pv[c] = *(const float4*)(pb + (size_t)c * N);

        int kls[4] = { kl4.x, kl4.y, kl4.z, kl4.w };
        int rls[4] = { rl4.x, rl4.y, rl4.z, rl4.w };
        float kms[4] = { km4.x, km4.y, km4.z, km4.w };
        float prs[CHAN][4];
#pragma unroll
        for (int c = 0; c < CHAN; c++) {
            prs[c][0] = pv[c].x; prs[c][1] = pv[c].y;
            prs[c][2] = pv[c].z; prs[c][3] = pv[c].w;
        }
#pragma unroll
        for (int j = 0; j < 4; j++) {
            const int kl = kls[j], rl = rls[j];
            local_kmax = max(local_kmax, kl);
            atomicAdd(&s_ksum[kl], kms[j]);
            atomicAdd(&s_rsum[rl], kms[j]);
#pragma unroll
            for (int c = 0; c < CHAN; c++) atomicAdd(&s_psum[kl][c], prs[c][j]);
        }
    } else if (n0 < N) {
        const float* pb = pred + (size_t)b * CHAN * N;
        for (int j = 0; j < PXPT; j++) {
            const int n = n0 + j;
            if (n >= N) break;
            const int kl = klab[base + n], rl = rlab[base + n];
            const float km = kmask[base + n];
            local_kmax = max(local_kmax, kl);
            atomicAdd(&s_ksum[kl], km);
            atomicAdd(&s_rsum[rl], km);
            for (int c = 0; c < CHAN; c++) atomicAdd(&s_psum[kl][c], pb[(size_t)c * N + n]);
        }
    }
    __syncthreads();

    for (int i = t; i < NSEG; i += THREADS) {
        float vk = s_ksum[i], vr = s_rsum[i];
        if (vk != 0.f) atomicAdd(&g_ksum[b][i], vk);
        if (vr != 0.f) atomicAdd(&g_rsum[b][i], vr);
    }
    for (int i = t; i < NSEG * CHAN; i += THREADS) {
        float v = (&s_psum[0][0])[i];
        if (v != 0.f) atomicAdd(&g_psum[b][0][0] + i, v);
    }

    if (b == BATCH - 1) {
#pragma unroll
        for (int o = 16; o; o >>= 1)
            local_kmax = max(local_kmax, __shfl_xor_sync(0xffffffffu, local_kmax, o));
        if ((t & 31) == 0) atomicMax(&g_kmax, local_kmax);
    }
}

__global__ void __launch_bounds__(THREADS) pass2_kernel(
    const float* __restrict__ pred,   // [B, C, N]
    const float* __restrict__ rmask,  // [B, N]
    const int*   __restrict__ klab,   // [B, N]
    const int*   __restrict__ rlab,   // [B, N]
    int N)
{
    __shared__ float4 s_g[NSEG];      // normalized Gk per kernel-label
    __shared__ float  s_rinv[NSEG];   // 1/(rcard+1) per region-label
    __shared__ float  s_part[THREADS / 32];

    const int t = threadIdx.x;
    const int b = blockIdx.y;

    if (t < NSEG) {
        float invk = (t == 0) ? 0.f : 1.f / (g_ksum[b][t] + 1.f);
        float4 g;
        g.x = g_psum[b][t][0] * invk;
        g.y = g_psum[b][t][1] * invk;
        g.z = g_psum[b][t][2] * invk;
        g.w = g_psum[b][t][3] * invk;
        s_g[t] = g;
        s_rinv[t] = (t == 0) ? 1.f : 1.f / (g_rsum[b][t] + 1.f);
    }
    __syncthreads();

    float acc = 0.f;
    const int n0 = (blockIdx.x * THREADS + t) * PXPT;
    const size_t base = (size_t)b * N;

    if (n0 + PXPT <= N) {
        int4   kl4 = *(const int4*)(klab + base + n0);
        int4   rl4 = *(const int4*)(rlab + base + n0);
        float4 rm4 = *(const float4*)(rmask + base + n0);
        float4 pv[CHAN];
        const float* pb = pred + (size_t)b * CHAN * N + n0;
#pragma unroll
        for (int c = 0; c < CHAN; c++) pv[c] = *(const float4*)(pb + (size_t)c * N);

        int kls[4] = { kl4.x, kl4.y, kl4.z, kl4.w };
        int rls[4] = { rl4.x, rl4.y, rl4.z, rl4.w };
        float rms[4] = { rm4.x, rm4.y, rm4.z, rm4.w };
        float prs[CHAN][4];
#pragma unroll
        for (int c = 0; c < CHAN; c++) {
            prs[c][0] = pv[c].x; prs[c][1] = pv[c].y;
            prs[c][2] = pv[c].z; prs[c][3] = pv[c].w;
        }
#pragma unroll
        for (int j = 0; j < 4; j++) {
            const float4 g = s_g[kls[j]];
            const float gg[4] = { g.x, g.y, g.z, g.w };
            const float rm = rms[j];
            float n2 = 0.f;
#pragma unroll
            for (int c = 0; c < CHAN; c++) {
                float d = fmaf(prs[c][j], rm, -gg[c]);  // pred*rmask - Gk
                n2 = fmaf(d, d, n2);
            }
            float nr = sqrtf(n2);
            float dd = fmaxf(nr - 0.5f, 0.f);
            acc += __logf(fmaf(dd, dd, 1.f)) * s_rinv[rls[j]];
        }
    } else if (n0 < N) {
        const float* pb = pred + (size_t)b * CHAN * N;
        for (int j = 0; j < PXPT; j++) {
            const int n = n0 + j;
            if (n >= N) break;
            const float4 g = s_g[klab[base + n]];
            const float gg[4] = { g.x, g.y, g.z, g.w };
            const float rm = rmask[base + n];
            float n2 = 0.f;
            for (int c = 0; c < CHAN; c++) {
                float d = fmaf(pb[(size_t)c * N + n], rm, -gg[c]);
                n2 = fmaf(d, d, n2);
            }
            float nr = sqrtf(n2);
            float dd = fmaxf(nr - 0.5f, 0.f);
            acc += __logf(fmaf(dd, dd, 1.f)) * s_rinv[rlab[base + n]];
        }
    }

    // block reduction -> double atomic
#pragma unroll
    for (int o = 16; o; o >>= 1) acc += __shfl_xor_sync(0xffffffffu, acc, o);
    if ((t & 31) == 0) s_part[t >> 5] = acc;
    __syncthreads();
    if (t == 0) {
        float s = 0.f;
#pragma unroll
        for (int i = 0; i < THREADS / 32; i++) s += s_part[i];
        atomicAdd(&g_acc, (double)s);
    }
}

__global__ void finalize_kernel(float* __restrict__ out) {
    out[0] = (float)(g_acc / (double)g_kmax);
}

extern "C" void kernel_launch(void* const* d_in, const int* in_sizes, int n_in,
                              void* d_out, int out_size) {
    const float* pred  = (const float*)d_in[0];  // pred_similarities [B,C,H,W]
    const float* rmask = (const float*)d_in[1];  // regions_mask      [B,1,H,W]
    const float* kmask = (const float*)d_in[2];  // kernels_mask      [B,1,H,W]
    const int*   rlab  = (const int*)d_in[3];    // text_mask_ndi_labels
    const int*   klab  = (const int*)d_in[4];    // kernel_mask_ndi_labels

    const int N = in_sizes[1] / BATCH;  // H*W
    const int blocks = (N + THREADS * PXPT - 1) / (THREADS * PXPT);
    dim3 grid(blocks, BATCH);

    init_scratch<<<1, 1024>>>();
    pass1_kernel<<<grid, THREADS>>>(pred, kmask, klab, rlab, N);
    pass2_kernel<<<grid, THREADS>>>(pred, rmask, klab, rlab, N);
    finalize_kernel<<<1, 1>>>((float*)d_out);
}

// round 2
// speedup vs baseline: 1.4895x; 1.4895x over previous
#include <cuda_runtime.h>

// AggregationLoss on GB300 (sm_103a).
// Pass1: per-batch segment sums over 33 labels; 4-way replicated, bank-spread
//        shared tables -> global scratch.
// Pass2: per-pixel loss with per-channel shared LUTs, reverse batch order for
//        L2 reuse of pass1's tail; block reduction -> double accumulator.
// Finalize: writes scalar, then zeroes scratch for the next graph replay
//        (__device__ globals are zero-initialized at load, covering call #1).
//
// Shapes fixed by the problem: B=16, C=4, N = 736*736 = 541696.

#define BATCH 16
#define CHAN 4
#define NSEG 33
#define NQ 6          // q0=ksum, q1..q4=psum[c], q5=rsum
#define NREP 4        // shared-table replicas
#define THREADS 256
#define PXPT 4

// ---- device scratch (allocation-free; zero at module load) ----
__device__ float  g_tab[BATCH][NQ][NSEG];
__device__ int    g_kmax;
__device__ double g_acc;

__device__ __forceinline__ int tab_idx(int q, int r, int l) {
    return (q * NREP + r) * NSEG + l;
}

__global__ void __launch_bounds__(THREADS) pass1_kernel(
    const float* __restrict__ pred,   // [B, C, N]
    const float* __restrict__ kmask,  // [B, N]
    const int*   __restrict__ klab,   // [B, N]
    const int*   __restrict__ rlab,   // [B, N]
    int N)
{
    __shared__ float s_tab[NQ * NREP * NSEG];   // 792 floats, bank-spread

    const int t = threadIdx.x;
    const int b = blockIdx.y;
    const int r = t & (NREP - 1);

    for (int i = t; i < NQ * NREP * NSEG; i += THREADS) s_tab[i] = 0.f;
    __syncthreads();

    const int n0 = (blockIdx.x * THREADS + t) * PXPT;
    const size_t base = (size_t)b * N;
    int local_kmax = 0;

    if (n0 + PXPT <= N) {
        int4   kl4 = *(const int4*)(klab + base + n0);
        int4   rl4 = *(const int4*)(rlab + base + n0);
        float4 km4 = *(const float4*)(kmask + base + n0);
        float4 pv[CHAN];
        const float* pb = pred + (size_t)b * CHAN * N + n0;
#pragma unroll
        for (int c = 0; c < CHAN; c++) pv[c] = *(const float4*)(pb + (size_t)c * N);

        int kls[4] = { kl4.x, kl4.y, kl4.z, kl4.w };
        int rls[4] = { rl4.x, rl4.y, rl4.z, rl4.w };
        float kms[4] = { km4.x, km4.y, km4.z, km4.w };
        float prs[CHAN][4];
#pragma unroll
        for (int c = 0; c < CHAN; c++) {
            prs[c][0] = pv[c].x; prs[c][1] = pv[c].y;
            prs[c][2] = pv[c].z; prs[c][3] = pv[c].w;
        }
#pragma unroll
        for (int j = 0; j < 4; j++) {
            const int kl = kls[j], rl = rls[j];
            local_kmax = max(local_kmax, kl);
            atomicAdd(&s_tab[tab_idx(0, r, kl)], kms[j]);
#pragma unroll
            for (int c = 0; c < CHAN; c++)
                atomicAdd(&s_tab[tab_idx(1 + c, r, kl)], prs[c][j]);
            atomicAdd(&s_tab[tab_idx(5, r, rl)], kms[j]);
        }
    } else if (n0 < N) {
        const float* pb = pred + (size_t)b * CHAN * N;
        for (int j = 0; j < PXPT; j++) {
            const int n = n0 + j;
            if (n >= N) break;
            const int kl = klab[base + n], rl = rlab[base + n];
            const float km = kmask[base + n];
            local_kmax = max(local_kmax, kl);
            atomicAdd(&s_tab[tab_idx(0, r, kl)], km);
            for (int c = 0; c < CHAN; c++)
                atomicAdd(&s_tab[tab_idx(1 + c, r, kl)], pb[(size_t)c * N + n]);
            atomicAdd(&s_tab[tab_idx(5, r, rl)], km);
        }
    }
    __syncthreads();

    // flush: sum replicas, one global atomic per (q, l)
    for (int i = t; i < NQ * NSEG; i += THREADS) {
        const int q = i / NSEG, l = i % NSEG;
        float v = 0.f;
#pragma unroll
        for (int rr = 0; rr < NREP; rr++) v += s_tab[tab_idx(q, rr, l)];
        if (v != 0.f) atomicAdd(&g_tab[b][q][l], v);
    }

    if (b == BATCH - 1) {
#pragma unroll
        for (int o = 16; o; o >>= 1)
            local_kmax = max(local_kmax, __shfl_xor_sync(0xffffffffu, local_kmax, o));
        if ((t & 31) == 0) atomicMax(&g_kmax, local_kmax);
    }
}

__global__ void __launch_bounds__(THREADS) pass2_kernel(
    const float* __restrict__ pred,   // [B, C, N]
    const float* __restrict__ rmask,  // [B, N]
    const int*   __restrict__ klab,   // [B, N]
    const int*   __restrict__ rlab,   // [B, N]
    int N)
{
    __shared__ float s_gc[CHAN][NSEG];   // normalized Gk, per-channel (bank = label)
    __shared__ float s_rinv[NSEG];       // 1/(rcard+1)
    __shared__ float s_part[THREADS / 32];

    const int t = threadIdx.x;
    const int b = (BATCH - 1) - blockIdx.y;   // reverse order: reuse pass1's L2 tail

    if (t < NSEG) {
        const float invk = (t == 0) ? 0.f : 1.f / (g_tab[b][0][t] + 1.f);
#pragma unroll
        for (int c = 0; c < CHAN; c++) s_gc[c][t] = g_tab[b][1 + c][t] * invk;
        s_rinv[t] = (t == 0) ? 1.f : 1.f / (g_tab[b][5][t] + 1.f);
    }
    __syncthreads();

    float acc = 0.f;
    const int n0 = (blockIdx.x * THREADS + t) * PXPT;
    const size_t base = (size_t)b * N;

    if (n0 + PXPT <= N) {
        int4   kl4 = *(const int4*)(klab + base + n0);
        int4   rl4 = *(const int4*)(rlab + base + n0);
        float4 rm4 = *(const float4*)(rmask + base + n0);
        float4 pv[CHAN];
        const float* pb = pred + (size_t)b * CHAN * N + n0;
#pragma unroll
        for (int c = 0; c < CHAN; c++) pv[c] = *(const float4*)(pb + (size_t)c * N);

        int kls[4] = { kl4.x, kl4.y, kl4.z, kl4.w };
        int rls[4] = { rl4.x, rl4.y, rl4.z, rl4.w };
        float rms[4] = { rm4.x, rm4.y, rm4.z, rm4.w };
        float prs[CHAN][4];
#pragma unroll
        for (int c = 0; c < CHAN; c++) {
            prs[c][0] = pv[c].x; prs[c][1] = pv[c].y;
            prs[c][2] = pv[c].z; prs[c][3] = pv[c].w;
        }
#pragma unroll
        for (int j = 0; j < 4; j++) {
            const int kl = kls[j];
            const float rm = rms[j];
            float n2 = 0.f;
#pragma unroll
            for (int c = 0; c < CHAN; c++) {
                float d = fmaf(prs[c][j], rm, -s_gc[c][kl]);
                n2 = fmaf(d, d, n2);
            }
            float nr = sqrtf(n2);
            float dd = fmaxf(nr - 0.5f, 0.f);
            acc += __logf(fmaf(dd, dd, 1.f)) * s_rinv[rls[j]];
        }
    } else if (n0 < N) {
        const float* pb = pred + (size_t)b * CHAN * N;
        for (int j = 0; j < PXPT; j++) {
            const int n = n0 + j;
            if (n >= N) break;
            const int kl = klab[base + n];
            const float rm = rmask[base + n];
            float n2 = 0.f;
            for (int c = 0; c < CHAN; c++) {
                float d = fmaf(pb[(size_t)c * N + n], rm, -s_gc[c][kl]);
                n2 = fmaf(d, d, n2);
            }
            float nr = sqrtf(n2);
            float dd = fmaxf(nr - 0.5f, 0.f);
            acc += __logf(fmaf(dd, dd, 1.f)) * s_rinv[rlab[base + n]];
        }
    }

#pragma unroll
    for (int o = 16; o; o >>= 1) acc += __shfl_xor_sync(0xffffffffu, acc, o);
    if ((t & 31) == 0) s_part[t >> 5] = acc;
    __syncthreads();
    if (t == 0) {
        float s = 0.f;
#pragma unroll
        for (int i = 0; i < THREADS / 32; i++) s += s_part[i];
        atomicAdd(&g_acc, (double)s);
    }
}

// Writes the result, then zeroes all scratch so the next graph replay starts
// clean (matches the zero-initialized state of the very first call).
__global__ void finalize_kernel(float* __restrict__ out) {
    const int t = threadIdx.x;
    if (t == 0) out[0] = (float)(g_acc / (double)g_kmax);
    __syncthreads();
    float* tp = &g_tab[0][0][0];
    for (int i = t; i < BATCH * NQ * NSEG; i += blockDim.x) tp[i] = 0.f;
    if (t == 0) { g_kmax = 0; g_acc = 0.0; }
}

extern "C" void kernel_launch(void* const* d_in, const int* in_sizes, int n_in,
                              void* d_out, int out_size) {
    const float* pred  = (const float*)d_in[0];
    const float* rmask = (const float*)d_in[1];
    const float* kmask = (const float*)d_in[2];
    const int*   rlab  = (const int*)d_in[3];
    const int*   klab  = (const int*)d_in[4];

    const int N = in_sizes[1] / BATCH;
    const int blocks = (N + THREADS * PXPT - 1) / (THREADS * PXPT);
    dim3 grid(blocks, BATCH);

    pass1_kernel<<<grid, THREADS>>>(pred, kmask, klab, rlab, N);
    pass2_kernel<<<grid, THREADS>>>(pred, rmask, klab, rlab, N);
    finalize_kernel<<<1, 256>>>((float*)d_out);
}